// round 6
// baseline (speedup 1.0000x reference)
#include <cuda_runtime.h>
#include <cuda_fp16.h>
#include <math.h>
#include <stdint.h>

#define NTOK 16384
#define DM 1024
typedef __half h16;

// ---------------- scratch (static device globals) ----------------
__device__ float g_kv[64 * 2048];
__device__ float g_cvec[1024];
__device__ float g_w2t[256 * 64];
__device__ float g_Hb[(size_t)NTOK * 256];

__device__ h16 g_Xhi[(size_t)NTOK * DM], g_Xlo[(size_t)NTOK * DM];
__device__ h16 g_Shi[(size_t)NTOK * DM], g_Slo[(size_t)NTOK * DM];
__device__ h16 g_Phi[(size_t)NTOK * DM], g_Plo[(size_t)NTOK * DM];
__device__ h16 g_Wshi[1024 * 1024], g_Wslo[1024 * 1024];
__device__ h16 g_Bmhi[1024 * 1024], g_Bmlo[1024 * 1024];
__device__ h16 g_W1hi[256 * 1024], g_W1lo[256 * 1024];

// ---------------- helpers ----------------
__device__ __forceinline__ uint32_t smem_u32(const void* p) {
    uint32_t a;
    asm("{ .reg .u64 t; cvta.to.shared.u64 t, %1; cvt.u32.u64 %0, t; }" : "=r"(a) : "l"(p));
    return a;
}
__device__ __forceinline__ void split2(float v, h16& hh, h16& ll) {
    hh = __float2half_rn(v);
    ll = __float2half_rn(v - __half2float(hh));
}
__device__ __forceinline__ uint32_t pkh(h16 a, h16 b) {
    __half2 t = __halves2half2(a, b);
    return *reinterpret_cast<uint32_t*>(&t);
}
__device__ __forceinline__ float gelu_exact(float x) {
    return 0.5f * x * (1.0f + erff(x * 0.70710678118654752f));
}

#define LDSM4(r, a)                                                               \
    asm volatile("ldmatrix.sync.aligned.m8n8.x4.shared.b16 {%0,%1,%2,%3}, [%4];"  \
                 : "=r"((r)[0]), "=r"((r)[1]), "=r"((r)[2]), "=r"((r)[3]) : "r"(a))

#define MMA16816(c, a, b)                                                         \
    asm volatile("mma.sync.aligned.m16n8k16.row.col.f32.f16.f16.f32 "             \
                 "{%0,%1,%2,%3},{%4,%5,%6,%7},{%8,%9},{%0,%1,%2,%3};"             \
                 : "+f"((c)[0]), "+f"((c)[1]), "+f"((c)[2]), "+f"((c)[3])         \
                 : "r"((a)[0]), "r"((a)[1]), "r"((a)[2]), "r"((a)[3]),            \
                   "r"((b)[0]), "r"((b)[1]))

#define CP16(d, s) \
    asm volatile("cp.async.cg.shared.global [%0], [%1], 16;" :: "r"(d), "l"(s))
#define CP_COMMIT() asm volatile("cp.async.commit_group;")
#define CP_WAIT1() asm volatile("cp.async.wait_group 1;")
#define CP_WAIT0() asm volatile("cp.async.wait_group 0;")

// ---------------- elementwise split ----------------
__global__ void split_kernel(const float* __restrict__ src, h16* __restrict__ hp,
                             h16* __restrict__ lp) {
    int i = blockIdx.x * 256 + threadIdx.x;
    float4 v = reinterpret_cast<const float4*>(src)[i];
    h16 h0, l0, h1, l1, h2, l2, h3, l3;
    split2(v.x, h0, l0); split2(v.y, h1, l1);
    split2(v.z, h2, l2); split2(v.w, h3, l3);
    reinterpret_cast<uint2*>(hp)[i] = make_uint2(pkh(h0, h1), pkh(h2, h3));
    reinterpret_cast<uint2*>(lp)[i] = make_uint2(pkh(l0, l1), pkh(l2, l3));
}

// ---------------- kv (merged): kv[e][i] = emb[e,:]@w_in[1024+i,:] + b_in[1024+i] ----------------
// grid 64, block 256; thread handles i = b*32 + tid/8, experts e = (tid&7) + 8*t
__global__ void kv_kernel(const float* __restrict__ w_in, const float* __restrict__ emb,
                          const float* __restrict__ b_in) {
    __shared__ float es[64][132];
    int i = blockIdx.x * 32 + (threadIdx.x >> 3);
    int el = threadIdx.x & 7;
    float acc[8];
#pragma unroll
    for (int t = 0; t < 8; t++) acc[t] = 0.f;
    for (int dc = 0; dc < 8; dc++) {
        __syncthreads();
        for (int idx = threadIdx.x; idx < 8192; idx += 256)
            es[idx >> 7][idx & 127] = emb[(idx >> 7) * 1024 + dc * 128 + (idx & 127)];
        __syncthreads();
        const float* wrow = w_in + (size_t)(1024 + i) * 1024 + dc * 128;
#pragma unroll 4
        for (int d4 = 0; d4 < 32; d4++) {
            float4 w4 = reinterpret_cast<const float4*>(wrow)[d4];
#pragma unroll
            for (int t = 0; t < 8; t++) {
                const float* ep = &es[el + 8 * t][d4 * 4];
                acc[t] = fmaf(w4.x, ep[0], acc[t]);
                acc[t] = fmaf(w4.y, ep[1], acc[t]);
                acc[t] = fmaf(w4.z, ep[2], acc[t]);
                acc[t] = fmaf(w4.w, ep[3], acc[t]);
            }
        }
    }
    float bias = b_in[1024 + i];
#pragma unroll
    for (int t = 0; t < 8; t++) g_kv[(el + 8 * t) * 2048 + i] = acc[t] + bias;
}

__global__ void transpose_kernel(const float* __restrict__ src, float* __restrict__ dst,
                                 int R, int C) {
    __shared__ float t[32][33];
    int c0 = blockIdx.x * 32, r0 = blockIdx.y * 32;
    int x = threadIdx.x, y = threadIdx.y;
#pragma unroll
    for (int j = 0; j < 32; j += 8) {
        int r = r0 + y + j, c = c0 + x;
        if (r < R && c < C) t[y + j][x] = src[(size_t)r * C + c];
    }
    __syncthreads();
#pragma unroll
    for (int j = 0; j < 32; j += 8) {
        int r = c0 + y + j, c = r0 + x;
        if (r < C && c < R) dst[(size_t)r * R + c] = t[x][y + j];
    }
}

// Wscore planes [he][d] + cvec (blockIdx.x==0)
__global__ void p1_kernel(const float* __restrict__ w_in, const float* __restrict__ b_in) {
    int h = blockIdx.y;
    int d0 = blockIdx.x * 128;
    __shared__ float wq_s[64][128];
    __shared__ float kq_s[64][64];
    for (int idx = threadIdx.x; idx < 64 * 32; idx += 256) {
        int row = idx >> 5, c4 = idx & 31;
        float4 v = reinterpret_cast<const float4*>(w_in + (size_t)(h * 64 + row) * 1024 + d0)[c4];
        *reinterpret_cast<float4*>(&wq_s[row][c4 * 4]) = v;
    }
    for (int idx = threadIdx.x; idx < 64 * 16; idx += 256) {
        int e = idx >> 4, c4 = idx & 15;
        float4 v = reinterpret_cast<const float4*>(g_kv + e * 2048 + h * 64)[c4];
        *reinterpret_cast<float4*>(&kq_s[e][c4 * 4]) = v;
    }
    __syncthreads();
    if (blockIdx.x == 0 && threadIdx.x < 64) {
        float s = 0.f;
        for (int dp = 0; dp < 64; dp++)
            s += b_in[h * 64 + dp] * kq_s[threadIdx.x][dp];
        g_cvec[h * 64 + threadIdx.x] = s * 0.125f;
    }
    int tx = threadIdx.x & 127, ez = threadIdx.x >> 7;
    float acc[32];
#pragma unroll
    for (int e = 0; e < 32; e++) acc[e] = 0.f;
    for (int dp = 0; dp < 64; dp++) {
        float w = wq_s[dp][tx];
#pragma unroll
        for (int e = 0; e < 32; e++) acc[e] = fmaf(w, kq_s[ez * 32 + e][dp], acc[e]);
    }
#pragma unroll
    for (int e = 0; e < 32; e++) {
        size_t idx = (size_t)(h * 64 + ez * 32 + e) * 1024 + d0 + tx;
        h16 a, b;
        split2(acc[e] * 0.125f, a, b);
        g_Wshi[idx] = a; g_Wslo[idx] = b;
    }
}

// Bmat planes [dout][he]
__global__ void p2_kernel(const float* __restrict__ w_out) {
    int h = blockIdx.y;
    int n0 = blockIdx.x * 128;
    __shared__ float wo_s[64][128];
    __shared__ float v_s[64][64];
    for (int idx = threadIdx.x; idx < 128 * 16; idx += 256) {
        int r = idx >> 4, c4 = idx & 15;
        float4 v = reinterpret_cast<const float4*>(w_out + (size_t)(n0 + r) * 1024 + h * 64)[c4];
        wo_s[c4 * 4 + 0][r] = v.x;
        wo_s[c4 * 4 + 1][r] = v.y;
        wo_s[c4 * 4 + 2][r] = v.z;
        wo_s[c4 * 4 + 3][r] = v.w;
    }
    for (int idx = threadIdx.x; idx < 64 * 16; idx += 256) {
        int e = idx >> 4, c4 = idx & 15;
        float4 v = reinterpret_cast<const float4*>(g_kv + e * 2048 + 1024 + h * 64)[c4];
        *reinterpret_cast<float4*>(&v_s[e][c4 * 4]) = v;
    }
    __syncthreads();
    int tx = threadIdx.x & 127, ez = threadIdx.x >> 7;
    float acc[32];
#pragma unroll
    for (int e = 0; e < 32; e++) acc[e] = 0.f;
    for (int dp = 0; dp < 64; dp++) {
        float w = wo_s[dp][tx];
#pragma unroll
        for (int e = 0; e < 32; e++) acc[e] = fmaf(w, v_s[ez * 32 + e][dp], acc[e]);
    }
#pragma unroll
    for (int e = 0; e < 32; e++) {
        size_t idx = (size_t)(n0 + tx) * 1024 + h * 64 + ez * 32 + e;
        h16 a, b;
        split2(acc[e], a, b);
        g_Bmhi[idx] = a; g_Bmlo[idx] = b;
    }
}

// ---------------- mma.sync split GEMM ----------------
// C[M,N] = Ah@Bh^T + Ah@Bl^T + Al@Bh^T   (A [M][K], B [N][K], K=1024)
// BM=256, BN=128, BK=64, 512 thr (16 warps, 4x4 grid of 64x32 warp tiles), 2-stage cp.async.
// MODE 0: +bias, softmax per 64-col head, split-write 2 fp16 planes
// MODE 1: +bias, split-write 2 fp16 planes
// MODE 2: +bias, gelu, fp32 write (NOUT cols total)
#define A_PLANE_B 32768       // 256 rows * 128 bytes
#define B_PLANE_B 16384       // 128 rows * 128 bytes
#define STAGE_B (2 * A_PLANE_B + 2 * B_PLANE_B)   // 96 KB
#define GEMM_SMEM (2 * STAGE_B)                   // 192 KB

template <int MODE, int NOUT>
__global__ void __launch_bounds__(512, 1)
gemm_mma(const h16* __restrict__ Ah, const h16* __restrict__ Al,
         const h16* __restrict__ Bh, const h16* __restrict__ Bl,
         const float* __restrict__ bias,
         h16* __restrict__ Ohi, h16* __restrict__ Olo, float* __restrict__ Of) {
    extern __shared__ char smem[];
    const uint32_t sb = smem_u32(smem);
    const int tid = threadIdx.x, lane = tid & 31, w = tid >> 5;
    const int wm = w >> 2, wn = w & 3;          // 4 x 4 warps (64 x 32 tiles)
    const int m0 = blockIdx.y * 256, n0 = blockIdx.x * 128;

    const h16* pb[4] = {Ah + (size_t)m0 * 1024, Al + (size_t)m0 * 1024,
                        Bh + (size_t)n0 * 1024, Bl + (size_t)n0 * 1024};

    auto load_tile = [&](int kt, int s) {
        uint32_t sbase = sb + s * STAGE_B;
#pragma unroll
        for (int p = 0; p < 2; p++) {
            const h16* src = pb[p] + kt * 64;
#pragma unroll
            for (int j = 0; j < 4; j++) {
                int gid = tid + 512 * j;          // 0..2047
                int row = gid >> 3, ch = gid & 7;
                CP16(sbase + p * A_PLANE_B + row * 128 + ((ch ^ (row & 7)) << 4),
                     src + (size_t)row * 1024 + ch * 8);
            }
        }
#pragma unroll
        for (int p = 0; p < 2; p++) {
            const h16* src = pb[2 + p] + kt * 64;
#pragma unroll
            for (int j = 0; j < 2; j++) {
                int gid = tid + 512 * j;          // 0..1023
                int row = gid >> 3, ch = gid & 7;
                CP16(sbase + 2 * A_PLANE_B + p * B_PLANE_B + row * 128 + ((ch ^ (row & 7)) << 4),
                     src + (size_t)row * 1024 + ch * 8);
            }
        }
        CP_COMMIT();
    };

    load_tile(0, 0);
    load_tile(1, 1);

    float acc[4][4][4];
#pragma unroll
    for (int mt = 0; mt < 4; mt++)
#pragma unroll
        for (int nt = 0; nt < 4; nt++)
#pragma unroll
            for (int r = 0; r < 4; r++) acc[mt][nt][r] = 0.f;

    const int gq = lane >> 3, li = lane & 7;

    for (int kt = 0; kt < 16; kt++) {
        CP_WAIT1();
        __syncthreads();
        uint32_t sbase = sb + (kt & 1) * STAGE_B;
#pragma unroll
        for (int ks = 0; ks < 4; ks++) {
            uint32_t af[2][4][4];
#pragma unroll
            for (int p = 0; p < 2; p++) {
#pragma unroll
                for (int mt = 0; mt < 4; mt++) {
                    int row = wm * 64 + mt * 16 + ((gq & 1) << 3) + li;
                    int kc = ks * 2 + (gq >> 1);
                    LDSM4(af[p][mt],
                          sbase + p * A_PLANE_B + row * 128 + ((kc ^ (row & 7)) << 4));
                }
            }
            uint32_t bf[4][2];
            // Bh fragments
#pragma unroll
            for (int np = 0; np < 2; np++) {
                int row = wn * 32 + np * 16 + ((gq >> 1) << 3) + li;
                int kc = ks * 2 + (gq & 1);
                uint32_t r4[4];
                LDSM4(r4, sbase + 2 * A_PLANE_B + row * 128 + ((kc ^ (row & 7)) << 4));
                bf[np * 2][0] = r4[0]; bf[np * 2][1] = r4[1];
                bf[np * 2 + 1][0] = r4[2]; bf[np * 2 + 1][1] = r4[3];
            }
#pragma unroll
            for (int mt = 0; mt < 4; mt++)
#pragma unroll
                for (int nt = 0; nt < 4; nt++) {
                    MMA16816(acc[mt][nt], af[0][mt], bf[nt]);  // hi*hi
                    MMA16816(acc[mt][nt], af[1][mt], bf[nt]);  // lo*hi
                }
            // Bl fragments
#pragma unroll
            for (int np = 0; np < 2; np++) {
                int row = wn * 32 + np * 16 + ((gq >> 1) << 3) + li;
                int kc = ks * 2 + (gq & 1);
                uint32_t r4[4];
                LDSM4(r4, sbase + 2 * A_PLANE_B + B_PLANE_B + row * 128 +
                          ((kc ^ (row & 7)) << 4));
                bf[np * 2][0] = r4[0]; bf[np * 2][1] = r4[1];
                bf[np * 2 + 1][0] = r4[2]; bf[np * 2 + 1][1] = r4[3];
            }
#pragma unroll
            for (int mt = 0; mt < 4; mt++)
#pragma unroll
                for (int nt = 0; nt < 4; nt++)
                    MMA16816(acc[mt][nt], af[0][mt], bf[nt]);  // hi*lo
        }
        __syncthreads();
        if (kt + 2 < 16) load_tile(kt + 2, kt & 1);
    }
    CP_WAIT0();
    __syncthreads();

    // ---- epilogue: stage C in smem so each thread owns a 64-col row segment ----
    float* Cs = reinterpret_cast<float*>(smem);
    const int P = 130;
#pragma unroll
    for (int mt = 0; mt < 4; mt++)
#pragma unroll
        for (int nt = 0; nt < 4; nt++) {
            int m = wm * 64 + mt * 16 + (lane >> 2);
            int n = wn * 32 + nt * 8 + ((lane & 3) << 1);
            *reinterpret_cast<float2*>(&Cs[m * P + n]) =
                make_float2(acc[mt][nt][0], acc[mt][nt][1]);
            *reinterpret_cast<float2*>(&Cs[(m + 8) * P + n]) =
                make_float2(acc[mt][nt][2], acc[mt][nt][3]);
        }
    __syncthreads();

    int r = tid >> 1, seg = tid & 1;
    float v[64];
#pragma unroll
    for (int c = 0; c < 64; c++)
        v[c] = Cs[r * P + seg * 64 + c] + __ldg(bias + n0 + seg * 64 + c);

    if (MODE == 0) {
        float mx = v[0];
#pragma unroll
        for (int c = 1; c < 64; c++) mx = fmaxf(mx, v[c]);
        float s = 0.f;
#pragma unroll
        for (int c = 0; c < 64; c++) { v[c] = expf(v[c] - mx); s += v[c]; }
        float inv = 1.0f / s;
#pragma unroll
        for (int c = 0; c < 64; c++) v[c] *= inv;
    }

    if (MODE == 2) {
        size_t o = (size_t)(m0 + r) * NOUT + n0 + seg * 64;
#pragma unroll
        for (int c = 0; c < 64; c += 4)
            *reinterpret_cast<float4*>(Of + o + c) =
                make_float4(gelu_exact(v[c]), gelu_exact(v[c + 1]),
                            gelu_exact(v[c + 2]), gelu_exact(v[c + 3]));
    } else {
        size_t o = (size_t)(m0 + r) * 1024 + n0 + seg * 64;
#pragma unroll
        for (int c0 = 0; c0 < 64; c0 += 8) {
            uint32_t hw[4], lw[4];
#pragma unroll
            for (int j = 0; j < 4; j++) {
                h16 a, b, c, d;
                split2(v[c0 + 2 * j], a, b);
                split2(v[c0 + 2 * j + 1], c, d);
                hw[j] = pkh(a, c);
                lw[j] = pkh(b, d);
            }
            *reinterpret_cast<uint4*>(Ohi + o + c0) = make_uint4(hw[0], hw[1], hw[2], hw[3]);
            *reinterpret_cast<uint4*>(Olo + o + c0) = make_uint4(lw[0], lw[1], lw[2], lw[3]);
        }
    }
}

// ---------------- gate logits + softmax + top2 (32 tokens/block, w2 in smem) ----------------
#define FINAL_SMEM ((16384 + 32 * 256) * 4)
__global__ void final_kernel(const float* __restrict__ b2, float* __restrict__ out) {
    extern __shared__ float fs[];
    float* w2s = fs;            // [j*64 + e]
    float* hs = fs + 16384;     // [k*256 + j]
    int tid = threadIdx.x;
    int t0 = blockIdx.x * 32;
    for (int idx = tid; idx < 16384; idx += 256) w2s[idx] = g_w2t[idx];
    for (int idx = tid; idx < 8192; idx += 256) hs[idx] = g_Hb[(size_t)t0 * 256 + idx];
    __syncthreads();
    int w = tid >> 5, l = tid & 31;
    float2 bb = *reinterpret_cast<const float2*>(b2 + 2 * l);
#pragma unroll
    for (int kk = 0; kk < 4; kk++) {
        int k = w * 4 + kk;
        const float* hrow = hs + k * 256;
        float a0 = bb.x, a1 = bb.y;
#pragma unroll 8
        for (int j = 0; j < 256; j++) {
            float hv = hrow[j];
            float2 ww = *reinterpret_cast<const float2*>(&w2s[j * 64 + 2 * l]);
            a0 = fmaf(hv, ww.x, a0);
            a1 = fmaf(hv, ww.y, a1);
        }
        // softmax over 64 (2 per lane)
        float m = fmaxf(a0, a1);
#pragma unroll
        for (int o = 16; o; o >>= 1) m = fmaxf(m, __shfl_xor_sync(0xffffffffu, m, o));
        float e0 = expf(a0 - m), e1 = expf(a1 - m);
        float s = e0 + e1;
#pragma unroll
        for (int o = 16; o; o >>= 1) s += __shfl_xor_sync(0xffffffffu, s, o);
        float inv = 1.0f / s;
        float p0 = e0 * inv, p1 = e1 * inv;
        // top-1 (ties -> lower index)
        float v = p0; int i = 2 * l;
        if (p1 > p0) { v = p1; i = 2 * l + 1; }
#pragma unroll
        for (int o = 16; o; o >>= 1) {
            float ov = __shfl_xor_sync(0xffffffffu, v, o);
            int oi = __shfl_xor_sync(0xffffffffu, i, o);
            if (ov > v || (ov == v && oi < i)) { v = ov; i = oi; }
        }
        float v1 = v; int i1 = i;
        // top-2
        float q0 = (i1 == 2 * l) ? -1.f : p0;
        float q1 = (i1 == 2 * l + 1) ? -1.f : p1;
        v = q0; i = 2 * l;
        if (q1 > q0) { v = q1; i = 2 * l + 1; }
#pragma unroll
        for (int o = 16; o; o >>= 1) {
            float ov = __shfl_xor_sync(0xffffffffu, v, o);
            int oi = __shfl_xor_sync(0xffffffffu, i, o);
            if (ov > v || (ov == v && oi < i)) { v = ov; i = oi; }
        }
        if (l == 0) {
            int t = t0 + k;
            float denom = v1 + v + 1e-8f;
            out[(size_t)t * 2 + 0] = (float)i1;
            out[(size_t)t * 2 + 1] = (float)i;
            out[(size_t)NTOK * 2 + (size_t)t * 2 + 0] = v1 / denom;
            out[(size_t)NTOK * 2 + (size_t)t * 2 + 1] = v / denom;
        }
    }
}

// ---------------- launch ----------------
extern "C" void kernel_launch(void* const* d_in, const int* in_sizes, int n_in,
                              void* d_out, int out_size) {
    (void)in_sizes; (void)n_in; (void)out_size;
    const float* x     = (const float*)d_in[0];
    const float* emb   = (const float*)d_in[1];
    const float* w_in  = (const float*)d_in[2];
    const float* b_in  = (const float*)d_in[3];
    const float* w_out = (const float*)d_in[4];
    const float* b_out = (const float*)d_in[5];
    const float* w1    = (const float*)d_in[6];
    const float* b1    = (const float*)d_in[7];
    const float* w2    = (const float*)d_in[8];
    const float* b2    = (const float*)d_in[9];
    float* out = (float*)d_out;

    float *pc, *pw2t, *pHb;
    h16 *pXhi, *pXlo, *pShi, *pSlo, *pPhi, *pPlo;
    h16 *pWshi, *pWslo, *pBmhi, *pBmlo, *pW1hi, *pW1lo;
    cudaGetSymbolAddress((void**)&pc, g_cvec);
    cudaGetSymbolAddress((void**)&pw2t, g_w2t);
    cudaGetSymbolAddress((void**)&pHb, g_Hb);
    cudaGetSymbolAddress((void**)&pXhi, g_Xhi);   cudaGetSymbolAddress((void**)&pXlo, g_Xlo);
    cudaGetSymbolAddress((void**)&pShi, g_Shi);   cudaGetSymbolAddress((void**)&pSlo, g_Slo);
    cudaGetSymbolAddress((void**)&pPhi, g_Phi);   cudaGetSymbolAddress((void**)&pPlo, g_Plo);
    cudaGetSymbolAddress((void**)&pWshi, g_Wshi); cudaGetSymbolAddress((void**)&pWslo, g_Wslo);
    cudaGetSymbolAddress((void**)&pBmhi, g_Bmhi); cudaGetSymbolAddress((void**)&pBmlo, g_Bmlo);
    cudaGetSymbolAddress((void**)&pW1hi, g_W1hi); cudaGetSymbolAddress((void**)&pW1lo, g_W1lo);

    cudaFuncSetAttribute(gemm_mma<0, 1024>, cudaFuncAttributeMaxDynamicSharedMemorySize, GEMM_SMEM);
    cudaFuncSetAttribute(gemm_mma<1, 1024>, cudaFuncAttributeMaxDynamicSharedMemorySize, GEMM_SMEM);
    cudaFuncSetAttribute(gemm_mma<2, 256>,  cudaFuncAttributeMaxDynamicSharedMemorySize, GEMM_SMEM);
    cudaFuncSetAttribute(final_kernel, cudaFuncAttributeMaxDynamicSharedMemorySize, FINAL_SMEM);

    // (1) split x, (2) kv, (3) Wscore+cvec  -> (4) gemm1 is the profiled launch
    split_kernel<<<(NTOK * DM / 4) / 256, 256>>>(x, pXhi, pXlo);
    kv_kernel<<<64, 256>>>(w_in, emb, b_in);
    p1_kernel<<<dim3(8, 16), 256>>>(w_in, b_in);

    // scores -> softmax -> attn planes
    gemm_mma<0, 1024><<<dim3(8, 64), 512, GEMM_SMEM>>>(
        pXhi, pXlo, pWshi, pWslo, pc, pShi, pSlo, nullptr);

    p2_kernel<<<dim3(8, 16), 256>>>(w_out);
    // attn_out planes
    gemm_mma<1, 1024><<<dim3(8, 64), 512, GEMM_SMEM>>>(
        pShi, pSlo, pBmhi, pBmlo, b_out, pPhi, pPlo, nullptr);

    split_kernel<<<(256 * 1024 / 4) / 256, 256>>>(w1, pW1hi, pW1lo);
    // gate hidden (gelu) fp32
    gemm_mma<2, 256><<<dim3(2, 64), 512, GEMM_SMEM>>>(
        pPhi, pPlo, pW1hi, pW1lo, b1, nullptr, nullptr, pHb);

    transpose_kernel<<<dim3(8, 2), dim3(32, 8)>>>(w2, pw2t, 64, 256);
    // logits + softmax + top2
    final_kernel<<<512, 256, FINAL_SMEM>>>(b2, out);
}

// round 8
// speedup vs baseline: 1.0610x; 1.0610x over previous
#include <cuda_runtime.h>
#include <cuda_fp16.h>
#include <math.h>
#include <stdint.h>

#define NTOK 16384
#define DM 1024
typedef __half h16;

// ---------------- scratch (static device globals) ----------------
__device__ float g_kv[64 * 2048];
__device__ float g_cvec[1024];
__device__ float g_w2t[256 * 64];
__device__ float g_Hb[(size_t)NTOK * 256];

__device__ h16 g_Xhi[(size_t)NTOK * DM], g_Xlo[(size_t)NTOK * DM];
__device__ h16 g_Shi[(size_t)NTOK * DM], g_Slo[(size_t)NTOK * DM];
__device__ h16 g_Phi[(size_t)NTOK * DM], g_Plo[(size_t)NTOK * DM];
__device__ h16 g_Wshi[1024 * 1024], g_Wslo[1024 * 1024];
__device__ h16 g_Bmhi[1024 * 1024], g_Bmlo[1024 * 1024];
__device__ h16 g_W1hi[256 * 1024], g_W1lo[256 * 1024];

// ---------------- helpers ----------------
__device__ __forceinline__ uint32_t smem_u32(const void* p) {
    uint32_t a;
    asm("{ .reg .u64 t; cvta.to.shared.u64 t, %1; cvt.u32.u64 %0, t; }" : "=r"(a) : "l"(p));
    return a;
}
__device__ __forceinline__ void split2(float v, h16& hh, h16& ll) {
    hh = __float2half_rn(v);
    ll = __float2half_rn(v - __half2float(hh));
}
__device__ __forceinline__ uint32_t pkh(h16 a, h16 b) {
    __half2 t = __halves2half2(a, b);
    return *reinterpret_cast<uint32_t*>(&t);
}
__device__ __forceinline__ float gelu_exact(float x) {
    return 0.5f * x * (1.0f + erff(x * 0.70710678118654752f));
}

#define LDSM4(r, a)                                                               \
    asm volatile("ldmatrix.sync.aligned.m8n8.x4.shared.b16 {%0,%1,%2,%3}, [%4];"  \
                 : "=r"((r)[0]), "=r"((r)[1]), "=r"((r)[2]), "=r"((r)[3]) : "r"(a))

#define MMA16816(c, a, b)                                                         \
    asm volatile("mma.sync.aligned.m16n8k16.row.col.f32.f16.f16.f32 "             \
                 "{%0,%1,%2,%3},{%4,%5,%6,%7},{%8,%9},{%0,%1,%2,%3};"             \
                 : "+f"((c)[0]), "+f"((c)[1]), "+f"((c)[2]), "+f"((c)[3])         \
                 : "r"((a)[0]), "r"((a)[1]), "r"((a)[2]), "r"((a)[3]),            \
                   "r"((b)[0]), "r"((b)[1]))

#define CP16(d, s) \
    asm volatile("cp.async.cg.shared.global [%0], [%1], 16;" :: "r"(d), "l"(s))
#define CP_COMMIT() asm volatile("cp.async.commit_group;")
#define CP_WAIT2() asm volatile("cp.async.wait_group 2;")
#define CP_WAIT0() asm volatile("cp.async.wait_group 0;")

// ---------------- elementwise split ----------------
__global__ void split_kernel(const float* __restrict__ src, h16* __restrict__ hp,
                             h16* __restrict__ lp) {
    int i = blockIdx.x * 256 + threadIdx.x;
    float4 v = reinterpret_cast<const float4*>(src)[i];
    h16 h0, l0, h1, l1, h2, l2, h3, l3;
    split2(v.x, h0, l0); split2(v.y, h1, l1);
    split2(v.z, h2, l2); split2(v.w, h3, l3);
    reinterpret_cast<uint2*>(hp)[i] = make_uint2(pkh(h0, h1), pkh(h2, h3));
    reinterpret_cast<uint2*>(lp)[i] = make_uint2(pkh(l0, l1), pkh(l2, l3));
}

// ---------------- kv: kv[e][i] = emb[e,:]@w_in[1024+i,:] + b_in[1024+i] ----------------
__global__ void kv_kernel(const float* __restrict__ w_in, const float* __restrict__ emb,
                          const float* __restrict__ b_in) {
    __shared__ float es[64][132];
    int i = blockIdx.x * 32 + (threadIdx.x >> 3);
    int el = threadIdx.x & 7;
    float acc[8];
#pragma unroll
    for (int t = 0; t < 8; t++) acc[t] = 0.f;
    for (int dc = 0; dc < 8; dc++) {
        __syncthreads();
        for (int idx = threadIdx.x; idx < 8192; idx += 256)
            es[idx >> 7][idx & 127] = emb[(idx >> 7) * 1024 + dc * 128 + (idx & 127)];
        __syncthreads();
        const float* wrow = w_in + (size_t)(1024 + i) * 1024 + dc * 128;
#pragma unroll 4
        for (int d4 = 0; d4 < 32; d4++) {
            float4 w4 = reinterpret_cast<const float4*>(wrow)[d4];
#pragma unroll
            for (int t = 0; t < 8; t++) {
                const float* ep = &es[el + 8 * t][d4 * 4];
                acc[t] = fmaf(w4.x, ep[0], acc[t]);
                acc[t] = fmaf(w4.y, ep[1], acc[t]);
                acc[t] = fmaf(w4.z, ep[2], acc[t]);
                acc[t] = fmaf(w4.w, ep[3], acc[t]);
            }
        }
    }
    float bias = b_in[1024 + i];
#pragma unroll
    for (int t = 0; t < 8; t++) g_kv[(el + 8 * t) * 2048 + i] = acc[t] + bias;
}

__global__ void transpose_kernel(const float* __restrict__ src, float* __restrict__ dst,
                                 int R, int C) {
    __shared__ float t[32][33];
    int c0 = blockIdx.x * 32, r0 = blockIdx.y * 32;
    int x = threadIdx.x, y = threadIdx.y;
#pragma unroll
    for (int j = 0; j < 32; j += 8) {
        int r = r0 + y + j, c = c0 + x;
        if (r < R && c < C) t[y + j][x] = src[(size_t)r * C + c];
    }
    __syncthreads();
#pragma unroll
    for (int j = 0; j < 32; j += 8) {
        int r = c0 + y + j, c = r0 + x;
        if (r < C && c < R) dst[(size_t)r * R + c] = t[x][y + j];
    }
}

// Wscore planes [he][d] + cvec (blockIdx.x==0)
__global__ void p1_kernel(const float* __restrict__ w_in, const float* __restrict__ b_in) {
    int h = blockIdx.y;
    int d0 = blockIdx.x * 128;
    __shared__ float wq_s[64][128];
    __shared__ float kq_s[64][64];
    for (int idx = threadIdx.x; idx < 64 * 32; idx += 256) {
        int row = idx >> 5, c4 = idx & 31;
        float4 v = reinterpret_cast<const float4*>(w_in + (size_t)(h * 64 + row) * 1024 + d0)[c4];
        *reinterpret_cast<float4*>(&wq_s[row][c4 * 4]) = v;
    }
    for (int idx = threadIdx.x; idx < 64 * 16; idx += 256) {
        int e = idx >> 4, c4 = idx & 15;
        float4 v = reinterpret_cast<const float4*>(g_kv + e * 2048 + h * 64)[c4];
        *reinterpret_cast<float4*>(&kq_s[e][c4 * 4]) = v;
    }
    __syncthreads();
    if (blockIdx.x == 0 && threadIdx.x < 64) {
        float s = 0.f;
        for (int dp = 0; dp < 64; dp++)
            s += b_in[h * 64 + dp] * kq_s[threadIdx.x][dp];
        g_cvec[h * 64 + threadIdx.x] = s * 0.125f;
    }
    int tx = threadIdx.x & 127, ez = threadIdx.x >> 7;
    float acc[32];
#pragma unroll
    for (int e = 0; e < 32; e++) acc[e] = 0.f;
    for (int dp = 0; dp < 64; dp++) {
        float w = wq_s[dp][tx];
#pragma unroll
        for (int e = 0; e < 32; e++) acc[e] = fmaf(w, kq_s[ez * 32 + e][dp], acc[e]);
    }
#pragma unroll
    for (int e = 0; e < 32; e++) {
        size_t idx = (size_t)(h * 64 + ez * 32 + e) * 1024 + d0 + tx;
        h16 a, b;
        split2(acc[e] * 0.125f, a, b);
        g_Wshi[idx] = a; g_Wslo[idx] = b;
    }
}

// Bmat planes [dout][he]
__global__ void p2_kernel(const float* __restrict__ w_out) {
    int h = blockIdx.y;
    int n0 = blockIdx.x * 128;
    __shared__ float wo_s[64][128];
    __shared__ float v_s[64][64];
    for (int idx = threadIdx.x; idx < 128 * 16; idx += 256) {
        int r = idx >> 4, c4 = idx & 15;
        float4 v = reinterpret_cast<const float4*>(w_out + (size_t)(n0 + r) * 1024 + h * 64)[c4];
        wo_s[c4 * 4 + 0][r] = v.x;
        wo_s[c4 * 4 + 1][r] = v.y;
        wo_s[c4 * 4 + 2][r] = v.z;
        wo_s[c4 * 4 + 3][r] = v.w;
    }
    for (int idx = threadIdx.x; idx < 64 * 16; idx += 256) {
        int e = idx >> 4, c4 = idx & 15;
        float4 v = reinterpret_cast<const float4*>(g_kv + e * 2048 + 1024 + h * 64)[c4];
        *reinterpret_cast<float4*>(&v_s[e][c4 * 4]) = v;
    }
    __syncthreads();
    int tx = threadIdx.x & 127, ez = threadIdx.x >> 7;
    float acc[32];
#pragma unroll
    for (int e = 0; e < 32; e++) acc[e] = 0.f;
    for (int dp = 0; dp < 64; dp++) {
        float w = wo_s[dp][tx];
#pragma unroll
        for (int e = 0; e < 32; e++) acc[e] = fmaf(w, v_s[ez * 32 + e][dp], acc[e]);
    }
#pragma unroll
    for (int e = 0; e < 32; e++) {
        size_t idx = (size_t)(n0 + tx) * 1024 + h * 64 + ez * 32 + e;
        h16 a, b;
        split2(acc[e], a, b);
        g_Bmhi[idx] = a; g_Bmlo[idx] = b;
    }
}

// ---------------- mma.sync split GEMM ----------------
// C[M,N] = Ah@Bh^T + Ah@Bl^T + Al@Bh^T   (A [M][K], B [N][K], K=1024)
// BM=BN=128, BK=32, 256 thr (8 warps, 2x4 grid of 64x32 warp tiles).
// Planes packed in 128B smem rows: chunks 0-3 = hi, 4-7 = lo. 3-stage cp.async,
// 96KB smem -> 2 CTAs/SM (independent barrier domains hide pipeline bubbles).
#define STAGE_B 32768                      // A 16KB + B 16KB
#define GEMM_SMEM (3 * STAGE_B)            // 96 KB

template <int MODE, int NOUT>
__global__ void __launch_bounds__(256, 2)
gemm_mma(const h16* __restrict__ Ah, const h16* __restrict__ Al,
         const h16* __restrict__ Bh, const h16* __restrict__ Bl,
         const float* __restrict__ bias,
         h16* __restrict__ Ohi, h16* __restrict__ Olo, float* __restrict__ Of) {
    extern __shared__ char smem[];
    const uint32_t sb = smem_u32(smem);
    const int tid = threadIdx.x, lane = tid & 31, w = tid >> 5;
    const int wm = w >> 2, wn = w & 3;          // 2 x 4 warps (64 x 32 tiles)
    const int m0 = blockIdx.y * 128, n0 = blockIdx.x * 128;

    const h16* pb[4] = {Ah + (size_t)m0 * 1024, Al + (size_t)m0 * 1024,
                        Bh + (size_t)n0 * 1024, Bl + (size_t)n0 * 1024};

    // stage layout: [A rows 0..127][B rows 0..127], each row 128B,
    // chunk ch (16B): ch<4 -> hi plane halves [kt*32 + (ch&3)*8..], ch>=4 -> lo plane
    auto load_tile = [&](int kt, int s) {
        uint32_t sbase = sb + s * STAGE_B;
#pragma unroll
        for (int j = 0; j < 8; j++) {
            int gid = tid + 256 * j;            // 0..2047 chunks
            int half = gid >> 10;               // 0 = A, 1 = B
            int lidx = gid & 1023;
            int row = lidx >> 3, ch = lidx & 7;
            int p = ch >> 2, kc = ch & 3;
            const h16* src = pb[half * 2 + p] + (size_t)row * 1024 + kt * 32 + kc * 8;
            CP16(sbase + half * 16384 + row * 128 + ((ch ^ (row & 7)) << 4), src);
        }
        CP_COMMIT();
    };

    load_tile(0, 0);
    load_tile(1, 1);
    load_tile(2, 2);

    float acc[4][4][4];
#pragma unroll
    for (int mt = 0; mt < 4; mt++)
#pragma unroll
        for (int nt = 0; nt < 4; nt++)
#pragma unroll
            for (int r = 0; r < 4; r++) acc[mt][nt][r] = 0.f;

    const int gq = lane >> 3, li = lane & 7;
    int stg = 0;

    for (int kt = 0; kt < 32; kt++) {
        CP_WAIT2();
        __syncthreads();
        uint32_t sbase = sb + stg * STAGE_B;
#pragma unroll
        for (int ks = 0; ks < 2; ks++) {
            uint32_t af[2][4][4];
#pragma unroll
            for (int p = 0; p < 2; p++) {
#pragma unroll
                for (int mt = 0; mt < 4; mt++) {
                    int row = wm * 64 + mt * 16 + ((gq & 1) << 3) + li;
                    int chunk = p * 4 + ks * 2 + (gq >> 1);
                    LDSM4(af[p][mt], sbase + row * 128 + ((chunk ^ (row & 7)) << 4));
                }
            }
            uint32_t bf[4][2];
            // Bh fragments
#pragma unroll
            for (int np = 0; np < 2; np++) {
                int row = wn * 32 + np * 16 + ((gq >> 1) << 3) + li;
                int chunk = ks * 2 + (gq & 1);
                uint32_t r4[4];
                LDSM4(r4, sbase + 16384 + row * 128 + ((chunk ^ (row & 7)) << 4));
                bf[np * 2][0] = r4[0]; bf[np * 2][1] = r4[1];
                bf[np * 2 + 1][0] = r4[2]; bf[np * 2 + 1][1] = r4[3];
            }
#pragma unroll
            for (int mt = 0; mt < 4; mt++)
#pragma unroll
                for (int nt = 0; nt < 4; nt++) {
                    MMA16816(acc[mt][nt], af[0][mt], bf[nt]);  // hi*hi
                    MMA16816(acc[mt][nt], af[1][mt], bf[nt]);  // lo*hi
                }
            // Bl fragments
#pragma unroll
            for (int np = 0; np < 2; np++) {
                int row = wn * 32 + np * 16 + ((gq >> 1) << 3) + li;
                int chunk = 4 + ks * 2 + (gq & 1);
                uint32_t r4[4];
                LDSM4(r4, sbase + 16384 + row * 128 + ((chunk ^ (row & 7)) << 4));
                bf[np * 2][0] = r4[0]; bf[np * 2][1] = r4[1];
                bf[np * 2 + 1][0] = r4[2]; bf[np * 2 + 1][1] = r4[3];
            }
#pragma unroll
            for (int mt = 0; mt < 4; mt++)
#pragma unroll
                for (int nt = 0; nt < 4; nt++)
                    MMA16816(acc[mt][nt], af[0][mt], bf[nt]);  // hi*lo
        }
        __syncthreads();
        if (kt + 3 < 32) load_tile(kt + 3, stg);
        stg = (stg == 2) ? 0 : stg + 1;
    }
    CP_WAIT0();
    __syncthreads();

    // ---- epilogue: stage C in smem so each thread owns a 64-col row segment ----
    float* Cs = reinterpret_cast<float*>(smem);
    const int P = 130;
#pragma unroll
    for (int mt = 0; mt < 4; mt++)
#pragma unroll
        for (int nt = 0; nt < 4; nt++) {
            int m = wm * 64 + mt * 16 + (lane >> 2);
            int n = wn * 32 + nt * 8 + ((lane & 3) << 1);
            *reinterpret_cast<float2*>(&Cs[m * P + n]) =
                make_float2(acc[mt][nt][0], acc[mt][nt][1]);
            *reinterpret_cast<float2*>(&Cs[(m + 8) * P + n]) =
                make_float2(acc[mt][nt][2], acc[mt][nt][3]);
        }
    __syncthreads();

    int r = tid >> 1, seg = tid & 1;
    float v[64];
#pragma unroll
    for (int c = 0; c < 64; c++)
        v[c] = Cs[r * P + seg * 64 + c] + __ldg(bias + n0 + seg * 64 + c);

    if (MODE == 0) {
        float mx = v[0];
#pragma unroll
        for (int c = 1; c < 64; c++) mx = fmaxf(mx, v[c]);
        float s = 0.f;
#pragma unroll
        for (int c = 0; c < 64; c++) { v[c] = expf(v[c] - mx); s += v[c]; }
        float inv = 1.0f / s;
#pragma unroll
        for (int c = 0; c < 64; c++) v[c] *= inv;
    }

    if (MODE == 2) {
        size_t o = (size_t)(m0 + r) * NOUT + n0 + seg * 64;
#pragma unroll
        for (int c = 0; c < 64; c += 4)
            *reinterpret_cast<float4*>(Of + o + c) =
                make_float4(gelu_exact(v[c]), gelu_exact(v[c + 1]),
                            gelu_exact(v[c + 2]), gelu_exact(v[c + 3]));
    } else {
        size_t o = (size_t)(m0 + r) * 1024 + n0 + seg * 64;
#pragma unroll
        for (int c0 = 0; c0 < 64; c0 += 8) {
            uint32_t hw[4], lw[4];
#pragma unroll
            for (int j = 0; j < 4; j++) {
                h16 a, b, c, d;
                split2(v[c0 + 2 * j], a, b);
                split2(v[c0 + 2 * j + 1], c, d);
                hw[j] = pkh(a, c);
                lw[j] = pkh(b, d);
            }
            *reinterpret_cast<uint4*>(Ohi + o + c0) = make_uint4(hw[0], hw[1], hw[2], hw[3]);
            *reinterpret_cast<uint4*>(Olo + o + c0) = make_uint4(lw[0], lw[1], lw[2], lw[3]);
        }
    }
}

// ---------------- gate logits + softmax + top2 (32 tokens/block, w2 in smem) ----------------
#define FINAL_SMEM ((16384 + 32 * 256) * 4)
__global__ void final_kernel(const float* __restrict__ b2, float* __restrict__ out) {
    extern __shared__ float fs[];
    float* w2s = fs;            // [j*64 + e]
    float* hs = fs + 16384;     // [k*256 + j]
    int tid = threadIdx.x;
    int t0 = blockIdx.x * 32;
    for (int idx = tid; idx < 16384; idx += 256) w2s[idx] = g_w2t[idx];
    for (int idx = tid; idx < 8192; idx += 256) hs[idx] = g_Hb[(size_t)t0 * 256 + idx];
    __syncthreads();
    int w = tid >> 5, l = tid & 31;
    float2 bb = *reinterpret_cast<const float2*>(b2 + 2 * l);
#pragma unroll
    for (int kk = 0; kk < 4; kk++) {
        int k = w * 4 + kk;
        const float* hrow = hs + k * 256;
        float a0 = bb.x, a1 = bb.y;
#pragma unroll 8
        for (int j = 0; j < 256; j++) {
            float hv = hrow[j];
            float2 ww = *reinterpret_cast<const float2*>(&w2s[j * 64 + 2 * l]);
            a0 = fmaf(hv, ww.x, a0);
            a1 = fmaf(hv, ww.y, a1);
        }
        float m = fmaxf(a0, a1);
#pragma unroll
        for (int o = 16; o; o >>= 1) m = fmaxf(m, __shfl_xor_sync(0xffffffffu, m, o));
        float e0 = expf(a0 - m), e1 = expf(a1 - m);
        float s = e0 + e1;
#pragma unroll
        for (int o = 16; o; o >>= 1) s += __shfl_xor_sync(0xffffffffu, s, o);
        float inv = 1.0f / s;
        float p0 = e0 * inv, p1 = e1 * inv;
        float v = p0; int i = 2 * l;
        if (p1 > p0) { v = p1; i = 2 * l + 1; }
#pragma unroll
        for (int o = 16; o; o >>= 1) {
            float ov = __shfl_xor_sync(0xffffffffu, v, o);
            int oi = __shfl_xor_sync(0xffffffffu, i, o);
            if (ov > v || (ov == v && oi < i)) { v = ov; i = oi; }
        }
        float v1 = v; int i1 = i;
        float q0 = (i1 == 2 * l) ? -1.f : p0;
        float q1 = (i1 == 2 * l + 1) ? -1.f : p1;
        v = q0; i = 2 * l;
        if (q1 > q0) { v = q1; i = 2 * l + 1; }
#pragma unroll
        for (int o = 16; o; o >>= 1) {
            float ov = __shfl_xor_sync(0xffffffffu, v, o);
            int oi = __shfl_xor_sync(0xffffffffu, i, o);
            if (ov > v || (ov == v && oi < i)) { v = ov; i = oi; }
        }
        if (l == 0) {
            int t = t0 + k;
            float denom = v1 + v + 1e-8f;
            out[(size_t)t * 2 + 0] = (float)i1;
            out[(size_t)t * 2 + 1] = (float)i;
            out[(size_t)NTOK * 2 + (size_t)t * 2 + 0] = v1 / denom;
            out[(size_t)NTOK * 2 + (size_t)t * 2 + 1] = v / denom;
        }
    }
}

// ---------------- launch ----------------
extern "C" void kernel_launch(void* const* d_in, const int* in_sizes, int n_in,
                              void* d_out, int out_size) {
    (void)in_sizes; (void)n_in; (void)out_size;
    const float* x     = (const float*)d_in[0];
    const float* emb   = (const float*)d_in[1];
    const float* w_in  = (const float*)d_in[2];
    const float* b_in  = (const float*)d_in[3];
    const float* w_out = (const float*)d_in[4];
    const float* b_out = (const float*)d_in[5];
    const float* w1    = (const float*)d_in[6];
    const float* b1    = (const float*)d_in[7];
    const float* w2    = (const float*)d_in[8];
    const float* b2    = (const float*)d_in[9];
    float* out = (float*)d_out;

    float *pc, *pw2t, *pHb;
    h16 *pXhi, *pXlo, *pShi, *pSlo, *pPhi, *pPlo;
    h16 *pWshi, *pWslo, *pBmhi, *pBmlo, *pW1hi, *pW1lo;
    cudaGetSymbolAddress((void**)&pc, g_cvec);
    cudaGetSymbolAddress((void**)&pw2t, g_w2t);
    cudaGetSymbolAddress((void**)&pHb, g_Hb);
    cudaGetSymbolAddress((void**)&pXhi, g_Xhi);   cudaGetSymbolAddress((void**)&pXlo, g_Xlo);
    cudaGetSymbolAddress((void**)&pShi, g_Shi);   cudaGetSymbolAddress((void**)&pSlo, g_Slo);
    cudaGetSymbolAddress((void**)&pPhi, g_Phi);   cudaGetSymbolAddress((void**)&pPlo, g_Plo);
    cudaGetSymbolAddress((void**)&pWshi, g_Wshi); cudaGetSymbolAddress((void**)&pWslo, g_Wslo);
    cudaGetSymbolAddress((void**)&pBmhi, g_Bmhi); cudaGetSymbolAddress((void**)&pBmlo, g_Bmlo);
    cudaGetSymbolAddress((void**)&pW1hi, g_W1hi); cudaGetSymbolAddress((void**)&pW1lo, g_W1lo);

    cudaFuncSetAttribute(gemm_mma<0, 1024>, cudaFuncAttributeMaxDynamicSharedMemorySize, GEMM_SMEM);
    cudaFuncSetAttribute(gemm_mma<1, 1024>, cudaFuncAttributeMaxDynamicSharedMemorySize, GEMM_SMEM);
    cudaFuncSetAttribute(gemm_mma<2, 256>,  cudaFuncAttributeMaxDynamicSharedMemorySize, GEMM_SMEM);
    cudaFuncSetAttribute(final_kernel, cudaFuncAttributeMaxDynamicSharedMemorySize, FINAL_SMEM);

    split_kernel<<<(NTOK * DM / 4) / 256, 256>>>(x, pXhi, pXlo);
    kv_kernel<<<64, 256>>>(w_in, emb, b_in);
    p1_kernel<<<dim3(8, 16), 256>>>(w_in, b_in);

    // scores -> softmax -> attn planes
    gemm_mma<0, 1024><<<dim3(8, 128), 256, GEMM_SMEM>>>(
        pXhi, pXlo, pWshi, pWslo, pc, pShi, pSlo, nullptr);

    p2_kernel<<<dim3(8, 16), 256>>>(w_out);
    // attn_out planes
    gemm_mma<1, 1024><<<dim3(8, 128), 256, GEMM_SMEM>>>(
        pShi, pSlo, pBmhi, pBmlo, b_out, pPhi, pPlo, nullptr);

    split_kernel<<<(256 * 1024 / 4) / 256, 256>>>(w1, pW1hi, pW1lo);
    // gate hidden (gelu) fp32
    gemm_mma<2, 256><<<dim3(2, 128), 256, GEMM_SMEM>>>(
        pPhi, pPlo, pW1hi, pW1lo, b1, nullptr, nullptr, pHb);

    transpose_kernel<<<dim3(8, 2), dim3(32, 8)>>>(w2, pw2t, 64, 256);
    // logits + softmax + top2
    final_kernel<<<512, 256, FINAL_SMEM>>>(b2, out);
}